// round 7
// baseline (speedup 1.0000x reference)
#include <cuda_runtime.h>
#include <cstdint>

// FlowDE R7: warp-specialized fused eval.
//  Block = 4 producer warps (3xTF32 mma QK -> logits -> online softmax -> P~
//  into double-buffered SMEM) + 4 consumer warps (scalar f32x2 PV with
//  flash-style rescale). Tensor pipe and FMA pipe run concurrently.
//  Each block covers 2 m-tiles (grid 16x32); qpart has 16 slices.

#define Nn 4096
#define Mm 4096
#define Dd 64
#define Tt 8
#define Hh 0.125f
#define S0c 0.001f
#define MCHUNK 16   // m superblocks (each = 2 tiles of 128)

typedef unsigned long long u64;
typedef uint32_t u32;

__device__ __forceinline__ u64 pack2(float lo, float hi) {
    u64 r; asm("mov.b64 %0, {%1, %2};" : "=l"(r) : "f"(lo), "f"(hi)); return r;
}
__device__ __forceinline__ void unpack2(float& lo, float& hi, u64 v) {
    asm("mov.b64 {%0, %1}, %2;" : "=f"(lo), "=f"(hi) : "l"(v));
}
__device__ __forceinline__ void ffma2(u64& d, u64 a, u64 b) {
    asm("fma.rn.f32x2 %0, %1, %2, %0;" : "+l"(d) : "l"(a), "l"(b));
}
__device__ __forceinline__ u64 mul2(u64 a, u64 b) {
    u64 d; asm("mul.rn.f32x2 %0, %1, %2;" : "=l"(d) : "l"(a), "l"(b)); return d;
}
__device__ __forceinline__ u32 to_tf32(float v) {
    u32 r; asm("cvt.rna.tf32.f32 %0, %1;" : "=r"(r) : "f"(v)); return r;
}
__device__ __forceinline__ void mma_tf32(float* d, const u32* a, const u32* b) {
    asm("mma.sync.aligned.m16n8k8.row.col.f32.tf32.tf32.f32 "
        "{%0,%1,%2,%3}, {%4,%5,%6,%7}, {%8,%9}, {%0,%1,%2,%3};"
        : "+f"(d[0]), "+f"(d[1]), "+f"(d[2]), "+f"(d[3])
        : "r"(a[0]), "r"(a[1]), "r"(a[2]), "r"(a[3]), "r"(b[0]), "r"(b[1]));
}
#define BAR_SYNC(id, cnt) \
    asm volatile("bar.sync %0, %1;" :: "r"(id), "r"(cnt) : "memory")
#define BAR_ARRIVE(id, cnt) \
    asm volatile("bar.arrive %0, %1;" :: "r"(id), "r"(cnt) : "memory")

// ---------------- globals -----------------------------------------------------
__device__ float g_xt[Nn * Dd];
__device__ float g_xeff[Nn * Dd];
__device__ float g_G1[Nn * Dd];
__device__ float g_x0sq[Mm];
__device__ float g_pmax[MCHUNK * Nn];
__device__ float g_psum[MCHUNK * Nn];
__device__ float g_rmax[Nn];
__device__ float g_rsum[Nn];
__device__ float g_qpart[(size_t)MCHUNK * Nn * Dd];   // 16MB
__device__ float g_xh32[Nn * Dd], g_xl32[Nn * Dd];
__device__ float g_x0h32[Mm * Dd], g_x0l32[Mm * Dd];

__device__ __forceinline__ void split_tf32(float v, int idx, float* h, float* l) {
    u32 hb = to_tf32(v);
    float hf = __uint_as_float(hb);
    u32 lb = to_tf32(v - hf);
    h[idx] = hf;
    l[idx] = __uint_as_float(lb);
}

// ---------------------------------------------------------------------------
__global__ void k_init(const float* __restrict__ z, const float* __restrict__ x0) {
    int idx = blockIdx.x * blockDim.x + threadIdx.x;
    if (idx < Nn * Dd) {
        float v = z[idx];
        g_xt[idx] = v;
        g_xeff[idx] = v;
        split_tf32(v, idx, g_xh32, g_xl32);
        split_tf32(x0[idx], idx, g_x0h32, g_x0l32);
    }
    if (idx < Mm) {
        const float4* r = reinterpret_cast<const float4*>(x0 + idx * Dd);
        float s = 0.f;
#pragma unroll
        for (int i = 0; i < Dd / 4; i++) {
            float4 v = r[i];
            s += v.x * v.x + v.y * v.y + v.z * v.z + v.w * v.w;
        }
        g_x0sq[idx] = s;
    }
}

// ---------------------------------------------------------------------------
// SMEM map:
//  [0,512)           x0sq (current tile)
//  [512,1024)        fbuf0 [128]
//  [1024,1536)       fbuf1 [128]
//  [2048,71680)      Ah|Al tf32 [128][68] each  (x n-side; loaded once)
//  [71680,106496)    Bh|Bl tf32 [64][68] each   (x0 m-side; per half)
//  [106496,140288)   PT0 [64 m][132 n] f32
//  [140288,174080)   PT1 [64 m][132 n] f32
//  [174080,208896)   X0f [128 m][68] f32        (per tile, consumer-owned)
// Named bars: 1=full0 2=full1 3=empty0 4=empty1 (cnt 256); 5=prod (128); 6=cons (128)
// ---------------------------------------------------------------------------
extern __shared__ char dsm[];

__global__ __launch_bounds__(256, 1) void k_fused(const float* __restrict__ x0,
                                                  float scale, float c2) {
    const int tid = threadIdx.x;
    const int bx = blockIdx.x;           // superblock (2 m-tiles)
    const int n0 = blockIdx.y * 128;

    float* x0sq_s = reinterpret_cast<float*>(dsm);
    float* fbuf0 = reinterpret_cast<float*>(dsm + 512);
    float* fbuf1 = reinterpret_cast<float*>(dsm + 1024);
    u32* Ah = reinterpret_cast<u32*>(dsm + 2048);
    u32* Al = Ah + 128 * 68;
    u32* Bh = reinterpret_cast<u32*>(dsm + 71680);
    u32* Bl = Bh + 64 * 68;
    float* PT0 = reinterpret_cast<float*>(dsm + 106496);
    float* PT1 = reinterpret_cast<float*>(dsm + 140288);
    float* X0f = reinterpret_cast<float*>(dsm + 174080);

    const int wid = tid >> 5;
    const int lane = tid & 31;
    const int g = lane >> 2;
    const int tg = lane & 3;

    if (wid < 4) {
        // ===================== PRODUCER =====================
        // load A (x n-side splits) once: 128 rows x 64 cols, h+l
#pragma unroll
        for (int it = 0; it < 16; it++) {
            int idx = tid + 128 * it;            // 0..2047 float4 slots
            int row = idx >> 4, q = idx & 15;
            float4 vh = *reinterpret_cast<const float4*>(
                &g_xh32[(n0 + row) * Dd + 4 * q]);
            float4 vl = *reinterpret_cast<const float4*>(
                &g_xl32[(n0 + row) * Dd + 4 * q]);
            *reinterpret_cast<float4*>(&Ah[row * 68 + 4 * q]) = vh;
            *reinterpret_cast<float4*>(&Al[row * 68 + 4 * q]) = vl;
        }

        float Mrun[2][2], Srun[2][2];
#pragma unroll
        for (int a = 0; a < 2; a++)
#pragma unroll
            for (int b = 0; b < 2; b++) { Mrun[a][b] = -1e30f; Srun[a][b] = 0.f; }

        for (int tile = 0; tile < 2; tile++) {
            int m0t = (2 * bx + tile) * 128;
            for (int half = 0; half < 2; half++) {
                int hidx = 2 * tile + half;
                int buf = hidx & 1;
                int mb = m0t + 64 * half;

                BAR_SYNC(5, 128);    // previous B fully consumed by all producers
                if (half == 0) x0sq_s[tid] = g_x0sq[m0t + tid];
#pragma unroll
                for (int it = 0; it < 8; it++) {
                    int idx = tid + 128 * it;        // 0..1023 float4 slots
                    int row = idx >> 4, q = idx & 15;
                    float4 vh = *reinterpret_cast<const float4*>(
                        &g_x0h32[(mb + row) * Dd + 4 * q]);
                    float4 vl = *reinterpret_cast<const float4*>(
                        &g_x0l32[(mb + row) * Dd + 4 * q]);
                    *reinterpret_cast<float4*>(&Bh[row * 68 + 4 * q]) = vh;
                    *reinterpret_cast<float4*>(&Bl[row * 68 + 4 * q]) = vl;
                }
                BAR_SYNC(5, 128);    // B (and x0sq) ready

                // QK mma: rows 32*wid..+31 (rf x m16), cols 0..63 (cm x n8)
                float c[2][8][4];
#pragma unroll
                for (int rf = 0; rf < 2; rf++)
#pragma unroll
                    for (int cm = 0; cm < 8; cm++)
#pragma unroll
                        for (int e = 0; e < 4; e++) c[rf][cm][e] = 0.f;

#pragma unroll
                for (int ks = 0; ks < 8; ks++) {
                    int co = 8 * ks + tg;
                    u32 ah[2][4], al[2][4];
#pragma unroll
                    for (int rf = 0; rf < 2; rf++) {
                        int rb = 32 * wid + 16 * rf;
                        ah[rf][0] = Ah[(rb + g) * 68 + co];
                        ah[rf][1] = Ah[(rb + g + 8) * 68 + co];
                        ah[rf][2] = Ah[(rb + g) * 68 + co + 4];
                        ah[rf][3] = Ah[(rb + g + 8) * 68 + co + 4];
                        al[rf][0] = Al[(rb + g) * 68 + co];
                        al[rf][1] = Al[(rb + g + 8) * 68 + co];
                        al[rf][2] = Al[(rb + g) * 68 + co + 4];
                        al[rf][3] = Al[(rb + g + 8) * 68 + co + 4];
                    }
#pragma unroll
                    for (int cm = 0; cm < 8; cm++) {
                        int cb = 8 * cm;
                        u32 bh[2], bl[2];
                        bh[0] = Bh[(cb + g) * 68 + co];
                        bh[1] = Bh[(cb + g) * 68 + co + 4];
                        bl[0] = Bl[(cb + g) * 68 + co];
                        bl[1] = Bl[(cb + g) * 68 + co + 4];
#pragma unroll
                        for (int rf = 0; rf < 2; rf++) {
                            mma_tf32(c[rf][cm], ah[rf], bh);
                            mma_tf32(c[rf][cm], ah[rf], bl);
                            mma_tf32(c[rf][cm], al[rf], bh);
                        }
                    }
                }

                // bias + per-row (half) max
                float lg[2][2][16];
                float mx[2][2];
#pragma unroll
                for (int rf = 0; rf < 2; rf++) {
#pragma unroll
                    for (int rh = 0; rh < 2; rh++) {
                        float m = -1e30f;
#pragma unroll
                        for (int cm = 0; cm < 8; cm++) {
                            int col = 8 * cm + 2 * tg;
                            float l0 = fmaf(scale, c[rf][cm][2 * rh],
                                            -c2 * x0sq_s[64 * half + col]);
                            float l1 = fmaf(scale, c[rf][cm][2 * rh + 1],
                                            -c2 * x0sq_s[64 * half + col + 1]);
                            lg[rf][rh][2 * cm] = l0;
                            lg[rf][rh][2 * cm + 1] = l1;
                            m = fmaxf(m, fmaxf(l0, l1));
                        }
#pragma unroll
                        for (int o = 1; o <= 2; o <<= 1)
                            m = fmaxf(m, __shfl_xor_sync(0xffffffffu, m, o));
                        mx[rf][rh] = m;
                    }
                }

                if (hidx >= 2) BAR_SYNC(3 + buf, 256);   // wait buffer empty
                float* PTb = buf ? PT1 : PT0;
                float* fb = buf ? fbuf1 : fbuf0;

#pragma unroll
                for (int rf = 0; rf < 2; rf++) {
#pragma unroll
                    for (int rh = 0; rh < 2; rh++) {
                        int row = 32 * wid + 16 * rf + 8 * rh + g;
                        float Mn = fmaxf(Mrun[rf][rh], mx[rf][rh]);
                        float f = __expf(Mrun[rf][rh] - Mn);
                        float s = 0.f;
#pragma unroll
                        for (int cm = 0; cm < 8; cm++) {
#pragma unroll
                            for (int e = 0; e < 2; e++) {
                                int col = 8 * cm + 2 * tg + e;
                                float ev = __expf(lg[rf][rh][2 * cm + e] - Mn);
                                PTb[col * 132 + row] = ev;
                                s += ev;
                            }
                        }
#pragma unroll
                        for (int o = 1; o <= 2; o <<= 1)
                            s += __shfl_xor_sync(0xffffffffu, s, o);
                        Srun[rf][rh] = Srun[rf][rh] * f + s;
                        Mrun[rf][rh] = Mn;
                        if (tg == 0) fb[row] = f;
                    }
                }
                BAR_ARRIVE(1 + buf, 256);   // buffer full
            }
        }
        // final stats
#pragma unroll
        for (int rf = 0; rf < 2; rf++)
#pragma unroll
            for (int rh = 0; rh < 2; rh++) {
                int row = 32 * wid + 16 * rf + 8 * rh + g;
                if (tg == 0) {
                    g_pmax[bx * Nn + n0 + row] = Mrun[rf][rh];
                    g_psum[bx * Nn + n0 + row] = Srun[rf][rh];
                }
            }
    } else {
        // ===================== CONSUMER =====================
        const int ctid = tid - 128;
        const int tn = ctid & 15;    // 8 n-rows each
        const int td = ctid >> 4;    // 8 d-cols each

        u64 acc[8][4];
#pragma unroll
        for (int i = 0; i < 8; i++)
#pragma unroll
            for (int j = 0; j < 4; j++) acc[i][j] = 0ull;

        for (int tile = 0; tile < 2; tile++) {
            int m0t = (2 * bx + tile) * 128;
            // load x0 f32 tile (rows = m of this tile)
#pragma unroll
            for (int it = 0; it < 16; it++) {
                int idx = ctid + 128 * it;       // 0..2047 float4 slots
                int row = idx >> 4, q = idx & 15;
                float4 v = *reinterpret_cast<const float4*>(
                    &x0[(m0t + row) * Dd + 4 * q]);
                *reinterpret_cast<float4*>(&X0f[row * 68 + 4 * q]) = v;
            }
            BAR_SYNC(6, 128);

            for (int half = 0; half < 2; half++) {
                int hidx = 2 * tile + half;
                int buf = hidx & 1;
                BAR_SYNC(1 + buf, 256);          // wait buffer full
                float* PTb = buf ? PT1 : PT0;
                float* fb = buf ? fbuf1 : fbuf0;

                // rescale accumulators
#pragma unroll
                for (int i = 0; i < 8; i++) {
                    float f = fb[8 * tn + i];
                    u64 ff = pack2(f, f);
#pragma unroll
                    for (int j = 0; j < 4; j++) acc[i][j] = mul2(acc[i][j], ff);
                }

#pragma unroll 4
                for (int k = 0; k < 64; k++) {
                    float4 a0 = *reinterpret_cast<const float4*>(
                        &PTb[k * 132 + 8 * tn]);
                    float4 a1 = *reinterpret_cast<const float4*>(
                        &PTb[k * 132 + 8 * tn + 4]);
                    float4 b0 = *reinterpret_cast<const float4*>(
                        &X0f[(64 * half + k) * 68 + 8 * td]);
                    float4 b1 = *reinterpret_cast<const float4*>(
                        &X0f[(64 * half + k) * 68 + 8 * td + 4]);
                    u64 bp[4] = {pack2(b0.x, b0.y), pack2(b0.z, b0.w),
                                 pack2(b1.x, b1.y), pack2(b1.z, b1.w)};
                    float a[8] = {a0.x, a0.y, a0.z, a0.w, a1.x, a1.y, a1.z, a1.w};
#pragma unroll
                    for (int i = 0; i < 8; i++) {
                        u64 ai = pack2(a[i], a[i]);
#pragma unroll
                        for (int j = 0; j < 4; j++) ffma2(acc[i][j], ai, bp[j]);
                    }
                }
                BAR_ARRIVE(3 + buf, 256);        // buffer empty
            }
        }

        // write qpart slice
#pragma unroll
        for (int i = 0; i < 8; i++) {
            float v0, v1, v2, v3, v4, v5, v6, v7;
            unpack2(v0, v1, acc[i][0]);
            unpack2(v2, v3, acc[i][1]);
            unpack2(v4, v5, acc[i][2]);
            unpack2(v6, v7, acc[i][3]);
            size_t off = ((size_t)bx * Nn + n0 + 8 * tn + i) * Dd + 8 * td;
            *reinterpret_cast<float4*>(&g_qpart[off]) = make_float4(v0, v1, v2, v3);
            *reinterpret_cast<float4*>(&g_qpart[off + 4]) = make_float4(v4, v5, v6, v7);
        }
    }
}

// ---------------------------------------------------------------------------
__global__ void k_reduce() {
    int n = blockIdx.x * blockDim.x + threadIdx.x;
    if (n >= Nn) return;
    float mx = -1e30f;
#pragma unroll
    for (int k = 0; k < MCHUNK; k++) mx = fmaxf(mx, g_pmax[k * Nn + n]);
    float sm = 0.f;
#pragma unroll
    for (int k = 0; k < MCHUNK; k++)
        sm += g_psum[k * Nn + n] * __expf(g_pmax[k * Nn + n] - mx);
    g_rmax[n] = mx;
    g_rsum[n] = sm;
}

// ---------------------------------------------------------------------------
__global__ void k_update(float sigmat, int first, int last, float* __restrict__ out) {
    int i4 = blockIdx.x * blockDim.x + threadIdx.x;
    if (i4 >= Nn * Dd / 4) return;
    int n = i4 >> 4;
    float rmax = g_rmax[n];
    float4 q = make_float4(0.f, 0.f, 0.f, 0.f);
#pragma unroll
    for (int s = 0; s < MCHUNK; s++) {
        float ef = __expf(g_pmax[s * Nn + n] - rmax);
        float4 v = *reinterpret_cast<const float4*>(
            &g_qpart[(size_t)s * Nn * Dd + 4 * i4]);
        q.x = fmaf(v.x, ef, q.x);
        q.y = fmaf(v.y, ef, q.y);
        q.z = fmaf(v.z, ef, q.z);
        q.w = fmaf(v.w, ef, q.w);
    }
    float inv = 1.f / g_rsum[n];
    float4 xe = *reinterpret_cast<const float4*>(&g_xeff[4 * i4]);
    float4 xt = *reinterpret_cast<const float4*>(&g_xt[4 * i4]);
    float4 G, xe2, xh, xl;
    float* Gp = &G.x; float* qp = &q.x; float* xep = &xe.x;
    float* xtp = &xt.x; float* xe2p = &xe2.x; float* xhp = &xh.x; float* xlp = &xl.x;
    float4 G1o;
    if (!first) G1o = *reinterpret_cast<const float4*>(&g_G1[4 * i4]);
    float* G1p = &G1o.x;
#pragma unroll
    for (int e = 0; e < 4; e++) {
        float Gv = ((1.f - S0c) * xep[e] - qp[e] * inv) / sigmat;
        Gp[e] = Gv;
        if (!first) xtp[e] = xtp[e] - (G1p[e] + Gv) * (Hh * 0.5f);
        float x2 = xtp[e] - Hh * Gv;
        xe2p[e] = x2;
        u32 hb = to_tf32(x2);
        float hf = __uint_as_float(hb);
        xhp[e] = hf;
        xlp[e] = __uint_as_float(to_tf32(x2 - hf));
    }
    if (!first) *reinterpret_cast<float4*>(&g_xt[4 * i4]) = xt;
    *reinterpret_cast<float4*>(&g_G1[4 * i4]) = G;
    *reinterpret_cast<float4*>(&g_xeff[4 * i4]) = xe2;
    *reinterpret_cast<float4*>(&g_xh32[4 * i4]) = xh;
    *reinterpret_cast<float4*>(&g_xl32[4 * i4]) = xl;
    if (last) *reinterpret_cast<float4*>(&out[4 * i4]) = xt;
}

// ---------------------------------------------------------------------------
extern "C" void kernel_launch(void* const* d_in, const int* in_sizes, int n_in,
                              void* d_out, int out_size) {
    const float* z = (const float*)d_in[0];
    const float* x0 = (const float*)d_in[1];

    const int SMEM_F = 208896;
    cudaFuncSetAttribute(k_fused, cudaFuncAttributeMaxDynamicSharedMemorySize,
                         SMEM_F);

    k_init<<<(Nn * Dd + 255) / 256, 256>>>(z, x0);

    for (int e = 0; e < Tt; e++) {
        float t = (e == 0) ? 1.0f : (float)(Tt - e) / (float)Tt;
        float alphat = 1.0f - t;
        float sigmat = S0c + (1.0f - S0c) * t;
        float inv2s2 = 1.0f / (sigmat * sigmat);
        float scale = alphat * inv2s2;
        float c2 = 0.5f * alphat * alphat * inv2s2;

        k_fused<<<dim3(MCHUNK, 32), 256, SMEM_F>>>(x0, scale, c2);
        k_reduce<<<Nn / 256, 256>>>();
        k_update<<<(Nn * Dd / 4) / 256, 256>>>(sigmat, e == 0, e == Tt - 1,
                                               (float*)d_out);
    }
}

// round 8
// speedup vs baseline: 1.2089x; 1.2089x over previous
#include <cuda_runtime.h>
#include <cstdint>

// FlowDE R8: R6 fused structure (8-warp QK mma -> softmax -> 8-warp PV), with
//  - two-pass epilogue through SMEM (no 64-reg logit array held across barriers)
//  - __launch_bounds__(256,2): 2 blocks/SM -> cross-block tensor/FMA overlap
//  - k_reduce folded into k_update
// Math: logits = scale*(x.x0^T) - c2*||x0||^2 (3xTF32 mma); qt = softmax @ x0
//       (f32x2 scalar PV); Heun, 8 evals.

#define Nn 4096
#define Mm 4096
#define Dd 64
#define Tt 8
#define Hh 0.125f
#define S0c 0.001f
#define MBLK 32
#define LDT 36
#define LDS_ 132
#define LDX 68

typedef unsigned long long u64;
typedef uint32_t u32;

__device__ __forceinline__ u64 pack2(float lo, float hi) {
    u64 r; asm("mov.b64 %0, {%1, %2};" : "=l"(r) : "f"(lo), "f"(hi)); return r;
}
__device__ __forceinline__ void unpack2(float& lo, float& hi, u64 v) {
    asm("mov.b64 {%0, %1}, %2;" : "=f"(lo), "=f"(hi) : "l"(v));
}
__device__ __forceinline__ void ffma2(u64& d, u64 a, u64 b) {
    asm("fma.rn.f32x2 %0, %1, %2, %0;" : "+l"(d) : "l"(a), "l"(b));
}
__device__ __forceinline__ u32 to_tf32(float v) {
    u32 r; asm("cvt.rna.tf32.f32 %0, %1;" : "=r"(r) : "f"(v)); return r;
}
__device__ __forceinline__ void mma_tf32(float* d, const u32* a, const u32* b) {
    asm("mma.sync.aligned.m16n8k8.row.col.f32.tf32.tf32.f32 "
        "{%0,%1,%2,%3}, {%4,%5,%6,%7}, {%8,%9}, {%0,%1,%2,%3};"
        : "+f"(d[0]), "+f"(d[1]), "+f"(d[2]), "+f"(d[3])
        : "r"(a[0]), "r"(a[1]), "r"(a[2]), "r"(a[3]), "r"(b[0]), "r"(b[1]));
}

// ---------------- globals -----------------------------------------------------
__device__ float g_xt[Nn * Dd];
__device__ float g_xeff[Nn * Dd];
__device__ float g_G1[Nn * Dd];
__device__ float g_x0sq[Mm];
__device__ float g_pmax[MBLK * Nn];
__device__ float g_psum[MBLK * Nn];
__device__ float g_qpart[(size_t)MBLK * Nn * Dd];   // 32MB
__device__ float g_xh32[Nn * Dd], g_xl32[Nn * Dd];
__device__ float g_x0h32[Mm * Dd], g_x0l32[Mm * Dd];

__device__ __forceinline__ void split_tf32(float v, int idx, float* h, float* l) {
    u32 hb = to_tf32(v);
    float hf = __uint_as_float(hb);
    u32 lb = to_tf32(v - hf);
    h[idx] = hf;
    l[idx] = __uint_as_float(lb);
}

// ---------------------------------------------------------------------------
__global__ void k_init(const float* __restrict__ z, const float* __restrict__ x0) {
    int idx = blockIdx.x * blockDim.x + threadIdx.x;
    if (idx < Nn * Dd) {
        float v = z[idx];
        g_xt[idx] = v;
        g_xeff[idx] = v;
        split_tf32(v, idx, g_xh32, g_xl32);
        split_tf32(x0[idx], idx, g_x0h32, g_x0l32);
    }
    if (idx < Mm) {
        const float4* r = reinterpret_cast<const float4*>(x0 + idx * Dd);
        float s = 0.f;
#pragma unroll
        for (int i = 0; i < Dd / 4; i++) {
            float4 v = r[i];
            s += v.x * v.x + v.y * v.y + v.z * v.z + v.w * v.w;
        }
        g_x0sq[idx] = s;
    }
}

// ---------------------------------------------------------------------------
// SMEM map (dynamic, 112640 B total):
//  [0,512)        x0sq
//  [1024,2048)    pm [128][2]
//  [2048,3072)    ps [128][2]
//  [4096,77824)   tf32 tiles Ah|Al|Bh|Bl  (aliased by PT [128c][132r] post-mma)
//  [77824,112640) X0f [128][LDX]
// ---------------------------------------------------------------------------
extern __shared__ char dsm[];

__global__ __launch_bounds__(256, 2) void k_fused(const float* __restrict__ x0,
                                                  float scale, float c2) {
    const int tid = threadIdx.x;
    const int m0 = blockIdx.x * 128;
    const int n0 = blockIdx.y * 128;

    float* x0sq_s = reinterpret_cast<float*>(dsm);
    float* pm = reinterpret_cast<float*>(dsm + 1024);
    float* ps = reinterpret_cast<float*>(dsm + 2048);
    u32* tiles = reinterpret_cast<u32*>(dsm + 4096);
    u32* Ah = tiles;
    u32* Al = tiles + 128 * LDT;
    u32* Bh = tiles + 2 * 128 * LDT;
    u32* Bl = tiles + 3 * 128 * LDT;
    float* PT = reinterpret_cast<float*>(dsm + 4096);        // alias
    float* X0f = reinterpret_cast<float*>(dsm + 77824);

    const int wid = tid >> 5;
    const int lane = tid & 31;
    const int wr = wid >> 1;
    const int wc = wid & 1;
    const int g = lane >> 2;
    const int tg = lane & 3;

    if (tid < 128) x0sq_s[tid] = g_x0sq[m0 + tid];

#pragma unroll
    for (int it = 0; it < 8; it++) {
        int idx = tid + 256 * it;
        int row = idx >> 4, q = idx & 15;
        float4 v = *reinterpret_cast<const float4*>(&x0[(m0 + row) * Dd + 4 * q]);
        *reinterpret_cast<float4*>(&X0f[row * LDX + 4 * q]) = v;
    }

    float c[2][8][4];
#pragma unroll
    for (int rf = 0; rf < 2; rf++)
#pragma unroll
        for (int cm = 0; cm < 8; cm++)
#pragma unroll
            for (int e = 0; e < 4; e++) c[rf][cm][e] = 0.f;

    const float* srcs[4] = {g_xh32 + (size_t)n0 * Dd, g_xl32 + (size_t)n0 * Dd,
                            g_x0h32 + (size_t)m0 * Dd, g_x0l32 + (size_t)m0 * Dd};

    for (int kk = 0; kk < 2; kk++) {
        __syncthreads();
#pragma unroll
        for (int t = 0; t < 4; t++) {
            u32* tb = tiles + t * 128 * LDT;
            const float* src = srcs[t];
#pragma unroll
            for (int it = 0; it < 4; it++) {
                int idx = tid + 256 * it;
                int row = idx >> 3, q = idx & 7;
                float4 v = *reinterpret_cast<const float4*>(
                    &src[row * Dd + kk * 32 + 4 * q]);
                *reinterpret_cast<float4*>(&tb[row * LDT + 4 * q]) = v;
            }
        }
        __syncthreads();

#pragma unroll
        for (int ks = 0; ks < 4; ks++) {
            u32 ah[2][4], al[2][4];
#pragma unroll
            for (int rf = 0; rf < 2; rf++) {
                int rb = 32 * wr + 16 * rf;
                int co = 8 * ks + tg;
                ah[rf][0] = Ah[(rb + g) * LDT + co];
                ah[rf][1] = Ah[(rb + g + 8) * LDT + co];
                ah[rf][2] = Ah[(rb + g) * LDT + co + 4];
                ah[rf][3] = Ah[(rb + g + 8) * LDT + co + 4];
                al[rf][0] = Al[(rb + g) * LDT + co];
                al[rf][1] = Al[(rb + g + 8) * LDT + co];
                al[rf][2] = Al[(rb + g) * LDT + co + 4];
                al[rf][3] = Al[(rb + g + 8) * LDT + co + 4];
            }
#pragma unroll
            for (int cm = 0; cm < 8; cm++) {
                int cb = 64 * wc + 8 * cm;
                int co = 8 * ks + tg;
                u32 bh[2], bl[2];
                bh[0] = Bh[(cb + g) * LDT + co];
                bh[1] = Bh[(cb + g) * LDT + co + 4];
                bl[0] = Bl[(cb + g) * LDT + co];
                bl[1] = Bl[(cb + g) * LDT + co + 4];
#pragma unroll
                for (int rf = 0; rf < 2; rf++) {
                    mma_tf32(c[rf][cm], ah[rf], bh);
                    mma_tf32(c[rf][cm], ah[rf], bl);
                    mma_tf32(c[rf][cm], al[rf], bh);
                }
            }
        }
    }

    __syncthreads();   // all mma operand reads done -> PT alias writable

    // ---- pass 1: raw logits -> PT (transposed), per-half row max -> pm ----
#pragma unroll
    for (int rf = 0; rf < 2; rf++) {
#pragma unroll
        for (int rh = 0; rh < 2; rh++) {
            int row = 32 * wr + 16 * rf + 8 * rh + g;
            float mx = -1e30f;
#pragma unroll
            for (int cm = 0; cm < 8; cm++) {
                int col = 64 * wc + 8 * cm + 2 * tg;
                float l0 = fmaf(scale, c[rf][cm][2 * rh], -c2 * x0sq_s[col]);
                float l1 = fmaf(scale, c[rf][cm][2 * rh + 1], -c2 * x0sq_s[col + 1]);
                PT[col * LDS_ + row] = l0;
                PT[(col + 1) * LDS_ + row] = l1;
                mx = fmaxf(mx, fmaxf(l0, l1));
            }
#pragma unroll
            for (int o = 1; o <= 2; o <<= 1)
                mx = fmaxf(mx, __shfl_xor_sync(0xffffffffu, mx, o));
            if (tg == 0) pm[row * 2 + wc] = mx;
        }
    }
    __syncthreads();

    // ---- pass 2: exp in place with full-row max, row sums ----
    {
        int r = tid >> 1;
        int h2 = tid & 1;
        float M = fmaxf(pm[r * 2], pm[r * 2 + 1]);
        float sm = 0.f;
#pragma unroll 8
        for (int cc = 0; cc < 64; cc++) {
            int col = 64 * h2 + cc;
            float v = __expf(PT[col * LDS_ + r] - M);
            PT[col * LDS_ + r] = v;
            sm += v;
        }
        ps[r * 2 + h2] = sm;
    }
    __syncthreads();

    if (tid < 128) {
        g_pmax[blockIdx.x * Nn + n0 + tid] = fmaxf(pm[tid * 2], pm[tid * 2 + 1]);
        g_psum[blockIdx.x * Nn + n0 + tid] = ps[tid * 2] + ps[tid * 2 + 1];
    }

    // ---- PV: qpart = P~ @ x0 ----
    const int tn = tid / 16;
    const int td = tid % 16;
    u64 acc[8][2];
#pragma unroll
    for (int i = 0; i < 8; i++) { acc[i][0] = 0ull; acc[i][1] = 0ull; }

#pragma unroll 4
    for (int k = 0; k < 128; k++) {
        float4 a0 = *reinterpret_cast<const float4*>(&PT[k * LDS_ + 8 * tn]);
        float4 a1 = *reinterpret_cast<const float4*>(&PT[k * LDS_ + 8 * tn + 4]);
        float4 b = *reinterpret_cast<const float4*>(&X0f[k * LDX + 4 * td]);
        u64 bp0 = pack2(b.x, b.y);
        u64 bp1 = pack2(b.z, b.w);
        float a[8] = {a0.x, a0.y, a0.z, a0.w, a1.x, a1.y, a1.z, a1.w};
#pragma unroll
        for (int i = 0; i < 8; i++) {
            u64 ai = pack2(a[i], a[i]);
            ffma2(acc[i][0], ai, bp0);
            ffma2(acc[i][1], ai, bp1);
        }
    }

#pragma unroll
    for (int i = 0; i < 8; i++) {
        float c0, c1, c2v, c3;
        unpack2(c0, c1, acc[i][0]);
        unpack2(c2v, c3, acc[i][1]);
        size_t off = (size_t)blockIdx.x * Nn * Dd + (n0 + 8 * tn + i) * Dd + 4 * td;
        *reinterpret_cast<float4*>(&g_qpart[off]) = make_float4(c0, c1, c2v, c3);
    }
}

// ---------------------------------------------------------------------------
// k_update: inline split-softmax reduce + Heun update, float4-vectorized.
// ---------------------------------------------------------------------------
__global__ void k_update(float sigmat, int first, int last, float* __restrict__ out) {
    int i4 = blockIdx.x * blockDim.x + threadIdx.x;
    if (i4 >= Nn * Dd / 4) return;
    int n = i4 >> 4;

    float mx = -1e30f;
#pragma unroll
    for (int s = 0; s < MBLK; s++) mx = fmaxf(mx, g_pmax[s * Nn + n]);
    float rsum = 0.f;
    float4 q = make_float4(0.f, 0.f, 0.f, 0.f);
#pragma unroll
    for (int s = 0; s < MBLK; s++) {
        float ef = __expf(g_pmax[s * Nn + n] - mx);
        rsum = fmaf(g_psum[s * Nn + n], ef, rsum);
        float4 v = *reinterpret_cast<const float4*>(
            &g_qpart[(size_t)s * Nn * Dd + 4 * i4]);
        q.x = fmaf(v.x, ef, q.x);
        q.y = fmaf(v.y, ef, q.y);
        q.z = fmaf(v.z, ef, q.z);
        q.w = fmaf(v.w, ef, q.w);
    }
    float inv = 1.f / rsum;
    float4 xe = *reinterpret_cast<const float4*>(&g_xeff[4 * i4]);
    float4 xt = *reinterpret_cast<const float4*>(&g_xt[4 * i4]);
    float4 G1o = make_float4(0.f, 0.f, 0.f, 0.f);
    if (!first) G1o = *reinterpret_cast<const float4*>(&g_G1[4 * i4]);
    float4 G, xe2, xh, xl;
    float* Gp = &G.x; float* qp = &q.x; float* xep = &xe.x;
    float* xtp = &xt.x; float* xe2p = &xe2.x; float* xhp = &xh.x; float* xlp = &xl.x;
    float* G1p = &G1o.x;
#pragma unroll
    for (int e = 0; e < 4; e++) {
        float Gv = ((1.f - S0c) * xep[e] - qp[e] * inv) / sigmat;
        Gp[e] = Gv;
        if (!first) xtp[e] = xtp[e] - (G1p[e] + Gv) * (Hh * 0.5f);
        float x2 = xtp[e] - Hh * Gv;
        xe2p[e] = x2;
        u32 hb = to_tf32(x2);
        float hf = __uint_as_float(hb);
        xhp[e] = hf;
        xlp[e] = __uint_as_float(to_tf32(x2 - hf));
    }
    if (!first) *reinterpret_cast<float4*>(&g_xt[4 * i4]) = xt;
    *reinterpret_cast<float4*>(&g_G1[4 * i4]) = G;
    *reinterpret_cast<float4*>(&g_xeff[4 * i4]) = xe2;
    *reinterpret_cast<float4*>(&g_xh32[4 * i4]) = xh;
    *reinterpret_cast<float4*>(&g_xl32[4 * i4]) = xl;
    if (last) *reinterpret_cast<float4*>(&out[4 * i4]) = xt;
}

// ---------------------------------------------------------------------------
extern "C" void kernel_launch(void* const* d_in, const int* in_sizes, int n_in,
                              void* d_out, int out_size) {
    const float* z = (const float*)d_in[0];
    const float* x0 = (const float*)d_in[1];

    const int SMEM_F = 77824 + 128 * LDX * 4;   // 112640
    cudaFuncSetAttribute(k_fused, cudaFuncAttributeMaxDynamicSharedMemorySize,
                         SMEM_F);

    k_init<<<(Nn * Dd + 255) / 256, 256>>>(z, x0);

    for (int e = 0; e < Tt; e++) {
        float t = (e == 0) ? 1.0f : (float)(Tt - e) / (float)Tt;
        float alphat = 1.0f - t;
        float sigmat = S0c + (1.0f - S0c) * t;
        float inv2s2 = 1.0f / (sigmat * sigmat);
        float scale = alphat * inv2s2;
        float c2 = 0.5f * alphat * alphat * inv2s2;

        k_fused<<<dim3(MBLK, 32), 256, SMEM_F>>>(x0, scale, c2);
        k_update<<<(Nn * Dd / 4) / 256, 256>>>(sigmat, e == 0, e == Tt - 1,
                                               (float*)d_out);
    }
}

// round 9
// speedup vs baseline: 1.5407x; 1.2745x over previous
#include <cuda_runtime.h>
#include <cstdint>

// FlowDE R9: both GEMMs on the tensor pipe.
//  QK: 3xTF32 mma (validated, unchanged). Softmax epilogue keeps logits in
//  registers, then exp+bf16x2-split+pair-pack directly into SMEM A-tiles.
//  PV: 3x bf16 m16n8k16 mma (ph*xh + ph*xl + pl*xh), x0 pre-split/transposed/
//  pair-packed in k_init. Scalar-FMA PV and its SMEM traffic are gone.

#define Nn 4096
#define Mm 4096
#define Dd 64
#define Tt 8
#define Hh 0.125f
#define S0c 0.001f
#define MBLK 32
#define LDT 36
#define LDP 68   // u32 pair-tile leading dim (128 rows x 64 pairs + pad)

typedef unsigned long long u64;
typedef uint32_t u32;

__device__ __forceinline__ u32 to_tf32(float v) {
    u32 r; asm("cvt.rna.tf32.f32 %0, %1;" : "=r"(r) : "f"(v)); return r;
}
__device__ __forceinline__ void mma_tf32(float* d, const u32* a, const u32* b) {
    asm("mma.sync.aligned.m16n8k8.row.col.f32.tf32.tf32.f32 "
        "{%0,%1,%2,%3}, {%4,%5,%6,%7}, {%8,%9}, {%0,%1,%2,%3};"
        : "+f"(d[0]), "+f"(d[1]), "+f"(d[2]), "+f"(d[3])
        : "r"(a[0]), "r"(a[1]), "r"(a[2]), "r"(a[3]), "r"(b[0]), "r"(b[1]));
}
__device__ __forceinline__ void mma_bf16(float* d, const u32* a, u32 b0, u32 b1) {
    asm("mma.sync.aligned.m16n8k16.row.col.f32.bf16.bf16.f32 "
        "{%0,%1,%2,%3}, {%4,%5,%6,%7}, {%8,%9}, {%0,%1,%2,%3};"
        : "+f"(d[0]), "+f"(d[1]), "+f"(d[2]), "+f"(d[3])
        : "r"(a[0]), "r"(a[1]), "r"(a[2]), "r"(a[3]), "r"(b0), "r"(b1));
}
// pack two f32 -> bf16x2 (lo = v0, hi = v1)
__device__ __forceinline__ u32 bf16pair(float v0, float v1) {
    u32 r; asm("cvt.rn.bf16x2.f32 %0, %1, %2;" : "=r"(r) : "f"(v1), "f"(v0));
    return r;
}
__device__ __forceinline__ float bf16lo_f(u32 p) { return __uint_as_float(p << 16); }
__device__ __forceinline__ float bf16hi_f(u32 p) {
    return __uint_as_float(p & 0xffff0000u);
}

// ---------------- globals -----------------------------------------------------
__device__ float g_xt[Nn * Dd];
__device__ float g_xeff[Nn * Dd];
__device__ float g_G1[Nn * Dd];
__device__ float g_x0sq[Mm];
__device__ float g_pmax[MBLK * Nn];
__device__ float g_psum[MBLK * Nn];
__device__ float g_qpart[(size_t)MBLK * Nn * Dd];
__device__ float g_xh32[Nn * Dd], g_xl32[Nn * Dd];     // tf32 split (QK A)
__device__ float g_x0h32[Mm * Dd], g_x0l32[Mm * Dd];   // tf32 split (QK B)
__device__ u32 g_x0bh[Dd * (Mm / 2)];  // x0^T bf16-high pairs [d][m/2]
__device__ u32 g_x0bl[Dd * (Mm / 2)];  // x0^T bf16-low  pairs [d][m/2]

__device__ __forceinline__ void split_tf32(float v, int idx, float* h, float* l) {
    u32 hb = to_tf32(v);
    float hf = __uint_as_float(hb);
    u32 lb = to_tf32(v - hf);
    h[idx] = hf;
    l[idx] = __uint_as_float(lb);
}

// ---------------------------------------------------------------------------
__global__ void k_init(const float* __restrict__ z, const float* __restrict__ x0) {
    int idx = blockIdx.x * blockDim.x + threadIdx.x;
    if (idx < Nn * Dd) {
        float v = z[idx];
        g_xt[idx] = v;
        g_xeff[idx] = v;
        split_tf32(v, idx, g_xh32, g_xl32);
        split_tf32(x0[idx], idx, g_x0h32, g_x0l32);
    }
    if (idx < Mm) {
        const float4* r = reinterpret_cast<const float4*>(x0 + idx * Dd);
        float s = 0.f;
#pragma unroll
        for (int i = 0; i < Dd / 4; i++) {
            float4 v = r[i];
            s += v.x * v.x + v.y * v.y + v.z * v.z + v.w * v.w;
        }
        g_x0sq[idx] = s;
    }
    // x0^T bf16 pair planes: [d][m/2]
    if (idx < Dd * (Mm / 2)) {
        int d = idx >> 11;           // / (Mm/2)
        int mp = idx & 2047;
        float v0 = x0[(2 * mp) * Dd + d];
        float v1 = x0[(2 * mp + 1) * Dd + d];
        u32 ph = bf16pair(v0, v1);
        float l0 = v0 - bf16lo_f(ph);
        float l1 = v1 - bf16hi_f(ph);
        g_x0bh[idx] = ph;
        g_x0bl[idx] = bf16pair(l0, l1);
    }
}

// ---------------------------------------------------------------------------
// SMEM map (dynamic, 112640 B):
//  [0,512)         x0sq
//  [1024,2048)     pm [128][2]
//  [2048,3072)     ps [128][2]
//  [4096,77824)    QK tf32 tiles Ah|Al|Bh|Bl (73728)
//                  -> post-QK aliased by Pph[128][LDP]u32 (34816) @4096
//                                       Ppl[128][LDP]u32 (34816) @38912
//  [77824,95232)   X0bh [64][LDP]u32
//  [95232,112640)  X0bl [64][LDP]u32
// ---------------------------------------------------------------------------
extern __shared__ char dsm[];

__global__ __launch_bounds__(256, 2) void k_fused(float scale, float c2) {
    const int tid = threadIdx.x;
    const int m0 = blockIdx.x * 128;
    const int n0 = blockIdx.y * 128;

    float* x0sq_s = reinterpret_cast<float*>(dsm);
    float* pm = reinterpret_cast<float*>(dsm + 1024);
    float* ps = reinterpret_cast<float*>(dsm + 2048);
    u32* tiles = reinterpret_cast<u32*>(dsm + 4096);
    u32* Ah = tiles;
    u32* Al = tiles + 128 * LDT;
    u32* Bh = tiles + 2 * 128 * LDT;
    u32* Bl = tiles + 3 * 128 * LDT;
    u32* Pph = reinterpret_cast<u32*>(dsm + 4096);    // alias (post-QK)
    u32* Ppl = reinterpret_cast<u32*>(dsm + 38912);   // alias (post-QK)
    u32* X0bh = reinterpret_cast<u32*>(dsm + 77824);
    u32* X0bl = reinterpret_cast<u32*>(dsm + 95232);

    const int wid = tid >> 5;
    const int lane = tid & 31;
    const int wr = wid >> 1;
    const int wc = wid & 1;
    const int g = lane >> 2;
    const int tg = lane & 3;

    if (tid < 128) x0sq_s[tid] = g_x0sq[m0 + tid];

    // load x0^T bf16 pair tiles (cols m0/2 .. m0/2+63)
#pragma unroll
    for (int it = 0; it < 16; it++) {
        int lin = tid + 256 * it;            // 0..4095
        int d = lin >> 6, mp = lin & 63;
        X0bh[d * LDP + mp] = g_x0bh[d * (Mm / 2) + m0 / 2 + mp];
        X0bl[d * LDP + mp] = g_x0bl[d * (Mm / 2) + m0 / 2 + mp];
    }

    float c[2][8][4];
#pragma unroll
    for (int rf = 0; rf < 2; rf++)
#pragma unroll
        for (int cm = 0; cm < 8; cm++)
#pragma unroll
            for (int e = 0; e < 4; e++) c[rf][cm][e] = 0.f;

    const float* srcs[4] = {g_xh32 + (size_t)n0 * Dd, g_xl32 + (size_t)n0 * Dd,
                            g_x0h32 + (size_t)m0 * Dd, g_x0l32 + (size_t)m0 * Dd};

    // ================= QK (tf32 3-product) =================
    for (int kk = 0; kk < 2; kk++) {
        __syncthreads();
#pragma unroll
        for (int t = 0; t < 4; t++) {
            u32* tb = tiles + t * 128 * LDT;
            const float* src = srcs[t];
#pragma unroll
            for (int it = 0; it < 4; it++) {
                int idx = tid + 256 * it;
                int row = idx >> 3, q = idx & 7;
                float4 v = *reinterpret_cast<const float4*>(
                    &src[row * Dd + kk * 32 + 4 * q]);
                *reinterpret_cast<float4*>(&tb[row * LDT + 4 * q]) = v;
            }
        }
        __syncthreads();

#pragma unroll
        for (int ks = 0; ks < 4; ks++) {
            u32 ah[2][4], al[2][4];
#pragma unroll
            for (int rf = 0; rf < 2; rf++) {
                int rb = 32 * wr + 16 * rf;
                int co = 8 * ks + tg;
                ah[rf][0] = Ah[(rb + g) * LDT + co];
                ah[rf][1] = Ah[(rb + g + 8) * LDT + co];
                ah[rf][2] = Ah[(rb + g) * LDT + co + 4];
                ah[rf][3] = Ah[(rb + g + 8) * LDT + co + 4];
                al[rf][0] = Al[(rb + g) * LDT + co];
                al[rf][1] = Al[(rb + g + 8) * LDT + co];
                al[rf][2] = Al[(rb + g) * LDT + co + 4];
                al[rf][3] = Al[(rb + g + 8) * LDT + co + 4];
            }
#pragma unroll
            for (int cm = 0; cm < 8; cm++) {
                int cb = 64 * wc + 8 * cm;
                int co = 8 * ks + tg;
                u32 bh[2], bl[2];
                bh[0] = Bh[(cb + g) * LDT + co];
                bh[1] = Bh[(cb + g) * LDT + co + 4];
                bl[0] = Bl[(cb + g) * LDT + co];
                bl[1] = Bl[(cb + g) * LDT + co + 4];
#pragma unroll
                for (int rf = 0; rf < 2; rf++) {
                    mma_tf32(c[rf][cm], ah[rf], bh);
                    mma_tf32(c[rf][cm], ah[rf], bl);
                    mma_tf32(c[rf][cm], al[rf], bh);
                }
            }
        }
    }
    __syncthreads();   // QK tile reads done -> Pp alias writable later

    // ---- pass 1: bias in place, per-row(half) max ----
#pragma unroll
    for (int rf = 0; rf < 2; rf++) {
#pragma unroll
        for (int rh = 0; rh < 2; rh++) {
            float mx = -1e30f;
#pragma unroll
            for (int cm = 0; cm < 8; cm++) {
                int col = 64 * wc + 8 * cm + 2 * tg;
                float l0 = fmaf(scale, c[rf][cm][2 * rh], -c2 * x0sq_s[col]);
                float l1 = fmaf(scale, c[rf][cm][2 * rh + 1], -c2 * x0sq_s[col + 1]);
                c[rf][cm][2 * rh] = l0;
                c[rf][cm][2 * rh + 1] = l1;
                mx = fmaxf(mx, fmaxf(l0, l1));
            }
#pragma unroll
            for (int o = 1; o <= 2; o <<= 1)
                mx = fmaxf(mx, __shfl_xor_sync(0xffffffffu, mx, o));
            if (tg == 0) pm[(32 * wr + 16 * rf + 8 * rh + g) * 2 + wc] = mx;
        }
    }
    __syncthreads();

    // ---- pass 2: exp, bf16x2 split, pair-pack into Pph/Ppl; row sums ----
#pragma unroll
    for (int rf = 0; rf < 2; rf++) {
#pragma unroll
        for (int rh = 0; rh < 2; rh++) {
            int row = 32 * wr + 16 * rf + 8 * rh + g;
            float M = fmaxf(pm[row * 2], pm[row * 2 + 1]);
            float sm = 0.f;
#pragma unroll
            for (int cm = 0; cm < 8; cm++) {
                float e0 = __expf(c[rf][cm][2 * rh] - M);
                float e1 = __expf(c[rf][cm][2 * rh + 1] - M);
                u32 ph = bf16pair(e0, e1);
                float l0 = e0 - bf16lo_f(ph);
                float l1 = e1 - bf16hi_f(ph);
                int cp = 32 * wc + 4 * cm + tg;      // pair index
                Pph[row * LDP + cp] = ph;
                Ppl[row * LDP + cp] = bf16pair(l0, l1);
                sm += e0 + e1;
            }
#pragma unroll
            for (int o = 1; o <= 2; o <<= 1)
                sm += __shfl_xor_sync(0xffffffffu, sm, o);
            if (tg == 0) ps[row * 2 + wc] = sm;
        }
    }
    __syncthreads();

    if (tid < 128) {
        g_pmax[blockIdx.x * Nn + n0 + tid] = fmaxf(pm[tid * 2], pm[tid * 2 + 1]);
        g_psum[blockIdx.x * Nn + n0 + tid] = ps[tid * 2] + ps[tid * 2 + 1];
    }

    // ================= PV (bf16 3-product) =================
    // output [128n][64d]; warp (wr2 0..3, wc2 0..1): rows 32*wr2, cols 32*wc2
    const int wr2 = wid >> 1;
    const int wc2 = wid & 1;
    float cc[2][4][4];
#pragma unroll
    for (int rf = 0; rf < 2; rf++)
#pragma unroll
        for (int cm = 0; cm < 4; cm++)
#pragma unroll
            for (int e = 0; e < 4; e++) cc[rf][cm][e] = 0.f;

#pragma unroll
    for (int ks = 0; ks < 8; ks++) {
        int kp = 8 * ks + tg;              // k pair index
        u32 pah[2][4], pal[2][4];
#pragma unroll
        for (int rf = 0; rf < 2; rf++) {
            int rb = 32 * wr2 + 16 * rf;
            pah[rf][0] = Pph[(rb + g) * LDP + kp];
            pah[rf][1] = Pph[(rb + g + 8) * LDP + kp];
            pah[rf][2] = Pph[(rb + g) * LDP + kp + 4];
            pah[rf][3] = Pph[(rb + g + 8) * LDP + kp + 4];
            pal[rf][0] = Ppl[(rb + g) * LDP + kp];
            pal[rf][1] = Ppl[(rb + g + 8) * LDP + kp];
            pal[rf][2] = Ppl[(rb + g) * LDP + kp + 4];
            pal[rf][3] = Ppl[(rb + g + 8) * LDP + kp + 4];
        }
#pragma unroll
        for (int cm = 0; cm < 4; cm++) {
            int cb = 32 * wc2 + 8 * cm;
            u32 bh0 = X0bh[(cb + g) * LDP + kp];
            u32 bh1 = X0bh[(cb + g) * LDP + kp + 4];
            u32 bl0 = X0bl[(cb + g) * LDP + kp];
            u32 bl1 = X0bl[(cb + g) * LDP + kp + 4];
#pragma unroll
            for (int rf = 0; rf < 2; rf++) {
                mma_bf16(cc[rf][cm], pah[rf], bh0, bh1);
                mma_bf16(cc[rf][cm], pah[rf], bl0, bl1);
                mma_bf16(cc[rf][cm], pal[rf], bh0, bh1);
            }
        }
    }

    // write qpart slice
#pragma unroll
    for (int rf = 0; rf < 2; rf++) {
#pragma unroll
        for (int cm = 0; cm < 4; cm++) {
            int row0 = 32 * wr2 + 16 * rf + g;
            int col = 32 * wc2 + 8 * cm + 2 * tg;
            size_t base = (size_t)blockIdx.x * Nn * Dd;
            *reinterpret_cast<float2*>(&g_qpart[base + (size_t)(n0 + row0) * Dd + col]) =
                make_float2(cc[rf][cm][0], cc[rf][cm][1]);
            *reinterpret_cast<float2*>(
                &g_qpart[base + (size_t)(n0 + row0 + 8) * Dd + col]) =
                make_float2(cc[rf][cm][2], cc[rf][cm][3]);
        }
    }
}

// ---------------------------------------------------------------------------
__global__ void k_update(float sigmat, int first, int last, float* __restrict__ out) {
    int i4 = blockIdx.x * blockDim.x + threadIdx.x;
    if (i4 >= Nn * Dd / 4) return;
    int n = i4 >> 4;

    float mx = -1e30f;
#pragma unroll
    for (int s = 0; s < MBLK; s++) mx = fmaxf(mx, g_pmax[s * Nn + n]);
    float rsum = 0.f;
    float4 q = make_float4(0.f, 0.f, 0.f, 0.f);
#pragma unroll
    for (int s = 0; s < MBLK; s++) {
        float ef = __expf(g_pmax[s * Nn + n] - mx);
        rsum = fmaf(g_psum[s * Nn + n], ef, rsum);
        float4 v = *reinterpret_cast<const float4*>(
            &g_qpart[(size_t)s * Nn * Dd + 4 * i4]);
        q.x = fmaf(v.x, ef, q.x);
        q.y = fmaf(v.y, ef, q.y);
        q.z = fmaf(v.z, ef, q.z);
        q.w = fmaf(v.w, ef, q.w);
    }
    float inv = 1.f / rsum;
    float4 xe = *reinterpret_cast<const float4*>(&g_xeff[4 * i4]);
    float4 xt = *reinterpret_cast<const float4*>(&g_xt[4 * i4]);
    float4 G1o = make_float4(0.f, 0.f, 0.f, 0.f);
    if (!first) G1o = *reinterpret_cast<const float4*>(&g_G1[4 * i4]);
    float4 G, xe2, xh, xl;
    float* Gp = &G.x; float* qp = &q.x; float* xep = &xe.x;
    float* xtp = &xt.x; float* xe2p = &xe2.x; float* xhp = &xh.x; float* xlp = &xl.x;
    float* G1p = &G1o.x;
#pragma unroll
    for (int e = 0; e < 4; e++) {
        float Gv = ((1.f - S0c) * xep[e] - qp[e] * inv) / sigmat;
        Gp[e] = Gv;
        if (!first) xtp[e] = xtp[e] - (G1p[e] + Gv) * (Hh * 0.5f);
        float x2 = xtp[e] - Hh * Gv;
        xe2p[e] = x2;
        u32 hb = to_tf32(x2);
        float hf = __uint_as_float(hb);
        xhp[e] = hf;
        xlp[e] = __uint_as_float(to_tf32(x2 - hf));
    }
    if (!first) *reinterpret_cast<float4*>(&g_xt[4 * i4]) = xt;
    *reinterpret_cast<float4*>(&g_G1[4 * i4]) = G;
    *reinterpret_cast<float4*>(&g_xeff[4 * i4]) = xe2;
    *reinterpret_cast<float4*>(&g_xh32[4 * i4]) = xh;
    *reinterpret_cast<float4*>(&g_xl32[4 * i4]) = xl;
    if (last) *reinterpret_cast<float4*>(&out[4 * i4]) = xt;
}

// ---------------------------------------------------------------------------
extern "C" void kernel_launch(void* const* d_in, const int* in_sizes, int n_in,
                              void* d_out, int out_size) {
    const float* z = (const float*)d_in[0];
    const float* x0 = (const float*)d_in[1];

    const int SMEM_F = 112640;
    cudaFuncSetAttribute(k_fused, cudaFuncAttributeMaxDynamicSharedMemorySize,
                         SMEM_F);

    k_init<<<(Nn * Dd + 255) / 256, 256>>>(z, x0);

    for (int e = 0; e < Tt; e++) {
        float t = (e == 0) ? 1.0f : (float)(Tt - e) / (float)Tt;
        float alphat = 1.0f - t;
        float sigmat = S0c + (1.0f - S0c) * t;
        float inv2s2 = 1.0f / (sigmat * sigmat);
        float scale = alphat * inv2s2;
        float c2 = 0.5f * alphat * alphat * inv2s2;

        k_fused<<<dim3(MBLK, 32), 256, SMEM_F>>>(scale, c2);
        k_update<<<(Nn * Dd / 4) / 256, 256>>>(sigmat, e == 0, e == Tt - 1,
                                               (float*)d_out);
    }
}